// round 16
// baseline (speedup 1.0000x reference)
#include <cuda_runtime.h>
#include <cstdint>

#define BATCH   4096
#define SEQ     200
#define EMB     128
#define VOCAB   100000
#define HALF_V  50000
#define GRID    592                    // 148 SMs x 4 CTAs -> fully co-resident
#define NWARPS  (GRID * 8)             // 4736
#define GTASKS  12500                  // GEMV tasks per vocab half (4 rows/task)
#define NA_TASKS (GTASKS + BATCH)      // phase A: GEMV-lo + compaction

// Scratch (zero-init at load; CIDX slots >= cnt never written -> stay 0 -> P[0], L1-hot)
__device__ __align__(16) float Pbuf[VOCAB * 2];
__device__ __align__(16) int   CIDX[BATCH * SEQ];
__device__ int                 CNT[BATCH];
__device__ unsigned            g_bar[2];     // monotonic barrier counters

__device__ __forceinline__ void grid_barrier(int b) {
    __syncthreads();
    if (threadIdx.x == 0) {
        __threadfence();
        unsigned a    = atomicAdd(&g_bar[b], 1u) + 1u;
        unsigned goal = ((a + GRID - 1u) / GRID) * GRID;   // this launch's cohort
        while (atomicAdd(&g_bar[b], 0u) < goal) __nanosleep(64);
        __threadfence();
    }
    __syncthreads();
}

__global__ __launch_bounds__(256, 4)
void fused_kernel(const float* __restrict__ emb,
                  const float* __restrict__ W,
                  const int*   __restrict__ x,
                  const float* __restrict__ bias,
                  float*       __restrict__ out)
{
    const int warp = threadIdx.x >> 5;
    const int lane = threadIdx.x & 31;
    const int wg   = blockIdx.x * 8 + warp;

    const int sub = lane & 15;          // float4 position pair (sub, sub+16)
    const int grp = lane >> 4;          // row within pair of rows

    const float4* emb4 = reinterpret_cast<const float4*>(emb);
    const float4* W4   = reinterpret_cast<const float4*>(W);
    float2* P2 = reinterpret_cast<float2*>(Pbuf);

    // Weights held in registers for the whole kernel (16 floats).
    const float4 w00 = __ldg(&W4[sub]);
    const float4 w01 = __ldg(&W4[16 + sub]);
    const float4 w10 = __ldg(&W4[32 + sub]);
    const float4 w11 = __ldg(&W4[48 + sub]);

    // GEMV for 4 rows: r0 = base+4t+grp, r1 = r0+2. 16 lanes per row.
    auto gemv4 = [&](int t, int base) {
        const int r0 = base + 4 * t + grp;
        const int r1 = r0 + 2;
        float4 e00 = __ldg(&emb4[r0 * 32 + sub]);
        float4 e01 = __ldg(&emb4[r0 * 32 + 16 + sub]);
        float4 e10 = __ldg(&emb4[r1 * 32 + sub]);
        float4 e11 = __ldg(&emb4[r1 * 32 + 16 + sub]);

        float dA0 = e00.x*w00.x + e00.y*w00.y + e00.z*w00.z + e00.w*w00.w
                  + e01.x*w01.x + e01.y*w01.y + e01.z*w01.z + e01.w*w01.w;
        float dA1 = e00.x*w10.x + e00.y*w10.y + e00.z*w10.z + e00.w*w10.w
                  + e01.x*w11.x + e01.y*w11.y + e01.z*w11.z + e01.w*w11.w;
        float dB0 = e10.x*w00.x + e10.y*w00.y + e10.z*w00.z + e10.w*w00.w
                  + e11.x*w01.x + e11.y*w01.y + e11.z*w01.z + e11.w*w01.w;
        float dB1 = e10.x*w10.x + e10.y*w10.y + e10.z*w10.z + e10.w*w10.w
                  + e11.x*w11.x + e11.y*w11.y + e11.z*w11.z + e11.w*w11.w;

        #pragma unroll
        for (int off = 8; off > 0; off >>= 1) {          // reduce within 16 lanes
            dA0 += __shfl_xor_sync(0xFFFFFFFFu, dA0, off);
            dA1 += __shfl_xor_sync(0xFFFFFFFFu, dA1, off);
            dB0 += __shfl_xor_sync(0xFFFFFFFFu, dB0, off);
            dB1 += __shfl_xor_sync(0xFFFFFFFFu, dB1, off);
        }
        if (sub == 0) {
            P2[r0] = make_float2(dA0, dA1);
            P2[r1] = make_float2(dB0, dB1);
        }
    };

    // ---------------- Phase A: GEMV vocab [0, 50k) + compaction ----------------
    for (int t = wg; t < NA_TASKS; t += NWARPS) {
        if (t < GTASKS) {
            gemv4(t, 0);
        } else {
            const int row = t - GTASKS;
            const int* xr = x + row * SEQ;
            int base = 0;
            #pragma unroll
            for (int c = 0; c < 7; c++) {
                int s   = 32 * c + lane;
                int idx = (s < SEQ) ? __ldg(&xr[s]) : -1;
                bool valid = (idx >= 0);
                unsigned bm = __ballot_sync(0xFFFFFFFFu, valid);
                if (valid)
                    CIDX[row * SEQ + base + __popc(bm & ((1u << lane) - 1u))] = idx;
                base += __popc(bm);
            }
            if (lane == 0) CNT[row] = base;              // >= 1
        }
    }
    grid_barrier(0);

    // ---------------- Phase B: gather pass 1 (idx < 50k) + GEMV [50k, 100k) ----
    const bool act = (lane < 25);
    int4 qa = make_int4(0, 0, 0, 0), qb = make_int4(0, 0, 0, 0);
    int  cnt = 0;
    float a0 = 0.f, a1 = 0.f;          // per-lane partials, live across barrier

    if (wg < BATCH) {
        cnt = __ldg(&CNT[wg]);
        const int4* cq = reinterpret_cast<const int4*>(CIDX + wg * SEQ);
        if (act) { qa = __ldg(&cq[lane]); qb = __ldg(&cq[25 + lane]); }

        const int sA = act ? 4 * lane : 200;             // inactive lanes -> masked
        #pragma unroll
        for (int j = 0; j < 4; j++) {
            int ia = (&qa.x)[j], ib = (&qb.x)[j];
            float ma = (sA + j < cnt && ia < HALF_V) ? 1.f : 0.f;   // ia >= 0 always
            float mb = (100 + sA + j < cnt && ib < HALF_V) ? 1.f : 0.f;
            float2 pa = __ldg(&P2[ma != 0.f ? ia : 0]);  // masked-off -> P[0], L1-hot
            float2 pb = __ldg(&P2[mb != 0.f ? ib : 0]);
            a0 += ma * pa.x + mb * pb.x;
            a1 += ma * pa.y + mb * pb.y;
        }
    }
    for (int t = wg; t < GTASKS; t += NWARPS) gemv4(t, HALF_V);
    grid_barrier(1);

    // ---------------- Phase C: gather pass 2 (idx >= 50k), finalize ------------
    if (wg < BATCH) {
        const int sA = act ? 4 * lane : 200;
        #pragma unroll
        for (int j = 0; j < 4; j++) {
            int ia = (&qa.x)[j], ib = (&qb.x)[j];
            float ma = (sA + j < cnt && ia >= HALF_V) ? 1.f : 0.f;
            float mb = (100 + sA + j < cnt && ib >= HALF_V) ? 1.f : 0.f;
            float2 pa = __ldg(&P2[ma != 0.f ? ia : 0]);
            float2 pb = __ldg(&P2[mb != 0.f ? ib : 0]);
            a0 += ma * pa.x + mb * pb.x;
            a1 += ma * pa.y + mb * pb.y;
        }
        #pragma unroll
        for (int off = 16; off > 0; off >>= 1) {
            a0 += __shfl_xor_sync(0xFFFFFFFFu, a0, off);
            a1 += __shfl_xor_sync(0xFFFFFFFFu, a1, off);
        }
        if (lane == 0) {
            float inv = 1.0f / (float)cnt;               // cnt >= 1
            out[wg * 2 + 0] = a0 * inv + __ldg(&bias[0]);
            out[wg * 2 + 1] = a1 * inv + __ldg(&bias[1]);
        }
    }
}

extern "C" void kernel_launch(void* const* d_in, const int* in_sizes, int n_in,
                              void* d_out, int out_size)
{
    const int* x     = (const int*)d_in[0];       // int32 [4096,200]
    const float* emb = (const float*)d_in[1];     // [100000,128]
    const float* W   = (const float*)d_in[2];     // [2,128]
    const float* b   = (const float*)d_in[3];     // [2]
    float* out       = (float*)d_out;             // [4096,2]

    fused_kernel<<<GRID, 256>>>(emb, W, x, b, out);
}

// round 17
// speedup vs baseline: 1.1915x; 1.1915x over previous
#include <cuda_runtime.h>
#include <cstdint>

#define BATCH 4096
#define SEQ   200
#define EMB   128
#define VOCAB 100000
#define NPRE  1563            // ceil(100000 / 64) precompute blocks
#define NCMP  512             // 512 blocks * 8 warps = 4096 rows compacted

// Scratch (recomputed every launch; CIDX slots >= cnt are masked and never loaded)
__device__ __align__(16) float Pbuf[VOCAB * 2];
__device__ __align__(16) int   CIDX[BATCH * SEQ];
__device__ int                 CNT[BATCH];

// ---- K1: heterogeneous. Blocks <NPRE: P = emb @ W^T. Blocks >=NPRE: compact indices. ----
__global__ __launch_bounds__(256)
void k1_precompute_compact(const float* __restrict__ emb,
                           const float* __restrict__ W,
                           const int* __restrict__ x)
{
    const int warp = threadIdx.x >> 5;
    const int lane = threadIdx.x & 31;

    if (blockIdx.x < NPRE) {
        const int warp_g = blockIdx.x * 8 + warp;
        const int sub = lane & 7;
        const int grp = lane >> 3;
        const int row_base = warp_g * 8;
        if (row_base >= VOCAB) return;

        const float4* emb4 = reinterpret_cast<const float4*>(emb);
        const float4* W4   = reinterpret_cast<const float4*>(W);

        float4 w0[4], w1[4];
        #pragma unroll
        for (int i = 0; i < 4; i++) {
            w0[i] = __ldg(&W4[sub + 8 * i]);
            w1[i] = __ldg(&W4[32 + sub + 8 * i]);
        }

        int rA = row_base + grp;
        int rB = row_base + 4 + grp;
        int cA = (rA < VOCAB) ? rA : VOCAB - 1;
        int cB = (rB < VOCAB) ? rB : VOCAB - 1;

        // Streaming, zero-reuse: evict-first loads (__ldlu) to keep L1 clean.
        float4 eA[4], eB[4];
        #pragma unroll
        for (int i = 0; i < 4; i++) {
            eA[i] = __ldlu(&emb4[cA * 32 + sub + 8 * i]);
            eB[i] = __ldlu(&emb4[cB * 32 + sub + 8 * i]);
        }

        float dA0 = 0.f, dA1 = 0.f, dB0 = 0.f, dB1 = 0.f;
        #pragma unroll
        for (int i = 0; i < 4; i++) {
            dA0 += eA[i].x * w0[i].x + eA[i].y * w0[i].y + eA[i].z * w0[i].z + eA[i].w * w0[i].w;
            dA1 += eA[i].x * w1[i].x + eA[i].y * w1[i].y + eA[i].z * w1[i].z + eA[i].w * w1[i].w;
            dB0 += eB[i].x * w0[i].x + eB[i].y * w0[i].y + eB[i].z * w0[i].z + eB[i].w * w0[i].w;
            dB1 += eB[i].x * w1[i].x + eB[i].y * w1[i].y + eB[i].z * w1[i].z + eB[i].w * w1[i].w;
        }

        #pragma unroll
        for (int off = 4; off > 0; off >>= 1) {
            dA0 += __shfl_xor_sync(0xFFFFFFFFu, dA0, off);
            dA1 += __shfl_xor_sync(0xFFFFFFFFu, dA1, off);
            dB0 += __shfl_xor_sync(0xFFFFFFFFu, dB0, off);
            dB1 += __shfl_xor_sync(0xFFFFFFFFu, dB1, off);
        }

        if (sub == 0) {
            float2* P2 = reinterpret_cast<float2*>(Pbuf);
            if (rA < VOCAB) P2[rA] = make_float2(dA0, dA1);
            if (rB < VOCAB) P2[rB] = make_float2(dB0, dB1);
        }
    } else {
        const int row = (blockIdx.x - NPRE) * 8 + warp;
        const int* xr = x + row * SEQ;
        int base = 0;
        #pragma unroll
        for (int c = 0; c < 7; c++) {
            int s   = 32 * c + lane;
            int idx = (s < SEQ) ? __ldg(&xr[s]) : -1;
            bool valid = (idx >= 0);
            unsigned bm = __ballot_sync(0xFFFFFFFFu, valid);
            if (valid)
                CIDX[row * SEQ + base + __popc(bm & ((1u << lane) - 1u))] = idx;
            base += __popc(bm);
        }
        if (lane == 0) CNT[row] = base;     // >= 1 (column 0 always valid)
    }
}

// ---- K2: gather compacted indices. 2 warps per row, predicated L2-only gathers. ----
__global__ __launch_bounds__(256)
void k2_gather(const float* __restrict__ bias,
               float* __restrict__ out)
{
    const int tid    = threadIdx.x;
    const int warp   = tid >> 5;            // 0..7
    const int lane   = tid & 31;
    const int warp_g = blockIdx.x * 8 + warp;
    const int row    = warp_g >> 1;         // 4 rows per block
    const int half   = warp_g & 1;

    const int* ci = CIDX + row * SEQ;
    const float2* P = reinterpret_cast<const float2*>(Pbuf);

    const int cnt = __ldg(&CNT[row]);

    // Slots for this half-warp: s0 + 64*k, k=0..3.
    const int s0 = lane + 32 * half;
    int i0 = __ldg(&ci[s0]);
    int i1 = __ldg(&ci[s0 + 64]);
    int i2 = __ldg(&ci[s0 + 128]);
    int i3 = (s0 + 192 < SEQ) ? __ldg(&ci[s0 + 192]) : 0;

    i0 = min(max(i0, 0), VOCAB - 1);
    i1 = min(max(i1, 0), VOCAB - 1);
    i2 = min(max(i2, 0), VOCAB - 1);
    i3 = min(max(i3, 0), VOCAB - 1);

    // Predicated L2-only gathers: masked slots issue NO load (no L1 fill, no L2 trip).
    float a0 = 0.f, a1 = 0.f;
    if (s0 < cnt)       { float2 p = __ldcg(&P[i0]); a0 += p.x; a1 += p.y; }
    if (s0 + 64 < cnt)  { float2 p = __ldcg(&P[i1]); a0 += p.x; a1 += p.y; }
    if (s0 + 128 < cnt) { float2 p = __ldcg(&P[i2]); a0 += p.x; a1 += p.y; }
    if (s0 + 192 < cnt) { float2 p = __ldcg(&P[i3]); a0 += p.x; a1 += p.y; }

    #pragma unroll
    for (int off = 16; off > 0; off >>= 1) {
        a0 += __shfl_xor_sync(0xFFFFFFFFu, a0, off);
        a1 += __shfl_xor_sync(0xFFFFFFFFu, a1, off);
    }

    __shared__ __align__(16) float2 part[8];
    __shared__ int scnt[4];
    if (lane == 0) {
        part[warp] = make_float2(a0, a1);
        if (half == 0) scnt[warp >> 1] = cnt;
    }
    __syncthreads();

    if (tid < 4) {
        float2 h0 = part[2 * tid];
        float2 h1 = part[2 * tid + 1];
        float inv = 1.0f / (float)scnt[tid];     // cnt >= 1
        int r = blockIdx.x * 4 + tid;
        out[r * 2 + 0] = (h0.x + h1.x) * inv + bias[0];
        out[r * 2 + 1] = (h0.y + h1.y) * inv + bias[1];
    }
}

extern "C" void kernel_launch(void* const* d_in, const int* in_sizes, int n_in,
                              void* d_out, int out_size)
{
    const int* x     = (const int*)d_in[0];       // int32 [4096,200]
    const float* emb = (const float*)d_in[1];     // [100000,128]
    const float* W   = (const float*)d_in[2];     // [2,128]
    const float* b   = (const float*)d_in[3];     // [2]
    float* out       = (float*)d_out;             // [4096,2]

    k1_precompute_compact<<<NPRE + NCMP, 256>>>(emb, W, x);
    k2_gather<<<BATCH / 4, 256>>>(b, out);
}